// round 15
// baseline (speedup 1.0000x reference)
#include <cuda_runtime.h>

// SpatialTransformer: affine grid + bilinear sampling.
// R8 structure (branch-free bottom-row loads + conditional top-row reuse)
// + cheap incremental L2 prefetch: the row k+3 bottom-corner address is
// approximated as (current bottom-corner offset + constant per-row delta),
// clamped into the batch image. ~6 ALU ops, ~2 regs — keeps R8's occupancy
// while converting critical LDGs from DRAM misses into L2 hits.
// image: [B=16, H=256, W=256, C=64] fp32, theta: [B=16, 6], out same shape.

constexpr int B_  = 16;
constexpr int H_  = 256;
constexpr int W_  = 256;
constexpr int C_  = 64;
constexpr int OH_ = 256;
constexpr int OW_ = 256;
constexpr int K_  = 8;   // oy pixels per thread (OH_/K_ = 32 strips)
constexpr int PF_ = 3;   // prefetch distance (rows)

__global__ __launch_bounds__(256) void stn_kernel(
    const float* __restrict__ img,
    const float* __restrict__ theta,
    float* __restrict__ out)
{
    const int gid = blockIdx.x * blockDim.x + threadIdx.x;
    const int c4  = gid & 15;          // float4 chunk (4 channels)
    const int t   = gid >> 4;          // pixel-column index
    const int ox  = t & (OW_ - 1);
    const int t2  = t >> 8;
    const int oyb = (t2 & (OH_ / K_ - 1)) * K_;
    const int b   = t2 >> 5;           // OH_/K_ = 32 -> shift 5

    const float th0 = __ldg(theta + b * 6 + 0);
    const float th1 = __ldg(theta + b * 6 + 1);
    const float th2 = __ldg(theta + b * 6 + 2);
    const float th3 = __ldg(theta + b * 6 + 3);
    const float th4 = __ldg(theta + b * 6 + 4);
    const float th5 = __ldg(theta + b * 6 + 5);

    // xt = th1*ys + (th0*xs + th2),  yt = th4*ys + (th3*xs + th5)
    const float xs = fmaf((float)ox, 2.0f / (OW_ - 1), -1.0f);
    const float xc = fmaf(th0, xs, th2);
    const float yc = fmaf(th3, xs, th5);

    // per-output-row sample deltas (texels); PF-row offset in float4 units
    const float dxr = th1 * ((float)W_ / (OW_ - 1));
    const float dyr = th4 * ((float)H_ / (OH_ - 1));
    const int pfoff = PF_ * (((int)rintf(dyr) << 12) + ((int)rintf(dxr) << 4));
    const int pfmax = H_ * W_ * (C_ / 4) - (C_ / 4);   // clamp bound (float4 units)

    // batch-folded base; per-texel float4 offset = (iy<<12) | (ix<<4)
    const float4* __restrict__ imgb =
        (const float4*)img + c4 + b * (H_ * W_ * (C_ / 4));
    float4* __restrict__ out4 =
        (float4*)out + (((b * OH_ + oyb) * OW_ + ox) * (C_ / 4) + c4);

    // carried state: previous bottom-row corner values + packed key
    float4 Pb, Pd;
    Pb = Pd = make_float4(0.f, 0.f, 0.f, 0.f);
    int pkey = -1;

#pragma unroll
    for (int k = 0; k < K_; k++) {
        const float ys = fmaf((float)(oyb + k), 2.0f / (OH_ - 1), -1.0f);
        const float x  = (fmaf(th1, ys, xc) + 1.0f) * (0.5f * (float)W_);
        const float y  = (fmaf(th4, ys, yc) + 1.0f) * (0.5f * (float)H_);

        const float xf = floorf(x), yf = floorf(y);
        const int ix0 = min(max((int)xf,     0), W_ - 1);
        const int ix1 = min(max((int)xf + 1, 0), W_ - 1);
        const int iy0 = min(max((int)yf,     0), H_ - 1);
        const int iy1 = min(max((int)yf + 1, 0), H_ - 1);

        const int x0o = ix0 << 4;
        const int x1o = ix1 << 4;
        const int r1o = iy1 << 12;

        // ---- cheap approximate L2 prefetch of row k+PF bottom corners ----
        {
            const int p0 = min(max(r1o + x0o + pfoff, 0), pfmax);
            const int p1 = min(max(r1o + x1o + pfoff, 0), pfmax);
            asm volatile("prefetch.global.L2 [%0];" :: "l"(imgb + p0));
            asm volatile("prefetch.global.L2 [%0];" :: "l"(imgb + p1));
        }

        // ---- unconditional bottom-row loads: branch-free, batchable ----
        const float4 Nb = __ldg(imgb + r1o + x0o);
        const float4 Nd = __ldg(imgb + r1o + x1o);

        // ---- top-row corners: reuse prev bottom pair on exact key match ----
        const int key = ix0 | (ix1 << 8) | (iy0 << 16);
        float4 Na, Nc;
        if (key == pkey) {
            Na = Pb;
            Nc = Pd;
        } else {
            const int r0o = iy0 << 12;
            Na = __ldg(imgb + r0o + x0o);
            Nc = __ldg(imgb + r0o + x1o);
        }
        pkey = ix0 | (ix1 << 8) | (iy1 << 16);

        // weights from CLIPPED corners cast back to float (matches reference)
        const float x0f = (float)ix0, x1f = (float)ix1;
        const float y0f = (float)iy0, y1f = (float)iy1;
        const float wa = (x1f - x) * (y1f - y);
        const float wb = (x1f - x) * (y - y0f);
        const float wc = (x - x0f) * (y1f - y);
        const float wd = (x - x0f) * (y - y0f);

        float4 o;
        o.x = fmaf(wa, Na.x, fmaf(wb, Nb.x, fmaf(wc, Nc.x, wd * Nd.x)));
        o.y = fmaf(wa, Na.y, fmaf(wb, Nb.y, fmaf(wc, Nc.y, wd * Nd.y)));
        o.z = fmaf(wa, Na.z, fmaf(wb, Nb.z, fmaf(wc, Nc.z, wd * Nd.z)));
        o.w = fmaf(wa, Na.w, fmaf(wb, Nb.w, fmaf(wc, Nc.w, wd * Nd.w)));

        *out4 = o;
        out4 += OW_ * (C_ / 4);

        Pb = Nb; Pd = Nd;
    }
}

extern "C" void kernel_launch(void* const* d_in, const int* in_sizes, int n_in,
                              void* d_out, int out_size)
{
    const float* img   = (const float*)d_in[0];
    const float* theta = (const float*)d_in[1];
    float* out = (float*)d_out;

    // threads = B*OW*(OH/K)*16 = 16*256*32*16 = 2,097,152 -> 8192 blocks
    const int threads = 256;
    const int blocks  = (B_ * OW_ * (OH_ / K_) * 16) / threads;

    stn_kernel<<<blocks, threads>>>(img, theta, out);
}

// round 16
// speedup vs baseline: 1.1355x; 1.1355x over previous
#include <cuda_runtime.h>

// SpatialTransformer: affine grid + bilinear sampling.
// R14 exactly (branch-free bottom-row loads + conditional top-row reuse +
// EXACT long-chain L2 prefetch of row k+3, which ptxas hoists early for real
// lead time) with one change: __launch_bounds__(256,5) caps regs at 48 so the
// SM fits 5 blocks (40 warps, ~62% occ) instead of 4 (42%), forcing remat of
// the cheap fp prefetch chains rather than holding them live in 64 regs.
// image: [B=16, H=256, W=256, C=64] fp32, theta: [B=16, 6], out same shape.

constexpr int B_  = 16;
constexpr int H_  = 256;
constexpr int W_  = 256;
constexpr int C_  = 64;
constexpr int OH_ = 256;
constexpr int OW_ = 256;
constexpr int K_  = 8;   // oy pixels per thread (OH_/K_ = 32 strips)
constexpr int PF_ = 3;   // prefetch distance (rows)

__global__ __launch_bounds__(256, 5) void stn_kernel(
    const float* __restrict__ img,
    const float* __restrict__ theta,
    float* __restrict__ out)
{
    const int gid = blockIdx.x * blockDim.x + threadIdx.x;
    const int c4  = gid & 15;          // float4 chunk (4 channels)
    const int t   = gid >> 4;          // pixel-column index
    const int ox  = t & (OW_ - 1);
    const int t2  = t >> 8;
    const int oyb = (t2 & (OH_ / K_ - 1)) * K_;
    const int b   = t2 >> 5;           // OH_/K_ = 32 -> shift 5

    const float th0 = __ldg(theta + b * 6 + 0);
    const float th1 = __ldg(theta + b * 6 + 1);
    const float th2 = __ldg(theta + b * 6 + 2);
    const float th3 = __ldg(theta + b * 6 + 3);
    const float th4 = __ldg(theta + b * 6 + 4);
    const float th5 = __ldg(theta + b * 6 + 5);

    // xt = th1*ys + (th0*xs + th2),  yt = th4*ys + (th3*xs + th5)
    const float xs = fmaf((float)ox, 2.0f / (OW_ - 1), -1.0f);
    const float xc = fmaf(th0, xs, th2);
    const float yc = fmaf(th3, xs, th5);

    // batch-folded base; per-texel float4 offset = (iy<<12) | (ix<<4)
    const float4* __restrict__ imgb =
        (const float4*)img + c4 + b * (H_ * W_ * (C_ / 4));
    float4* __restrict__ out4 =
        (float4*)out + (((b * OH_ + oyb) * OW_ + ox) * (C_ / 4) + c4);

    // carried state: previous bottom-row corner values + packed key
    float4 Pb, Pd;
    Pb = Pd = make_float4(0.f, 0.f, 0.f, 0.f);
    int pkey = -1;

#pragma unroll
    for (int k = 0; k < K_; k++) {
        // ---- L2 prefetch of row k+PF's bottom corners (exact addresses) ----
        if (k + PF_ < K_) {
            const float ysp = fmaf((float)(oyb + k + PF_), 2.0f / (OH_ - 1), -1.0f);
            const float xp  = (fmaf(th1, ysp, xc) + 1.0f) * (0.5f * (float)W_);
            const float yp  = (fmaf(th4, ysp, yc) + 1.0f) * (0.5f * (float)H_);
            const int pix0 = min(max((int)floorf(xp),     0), W_ - 1);
            const int pix1 = min(max((int)floorf(xp) + 1, 0), W_ - 1);
            const int piy1 = min(max((int)floorf(yp) + 1, 0), H_ - 1);
            const float4* pa = imgb + (piy1 << 12) + (pix0 << 4);
            const float4* pb = imgb + (piy1 << 12) + (pix1 << 4);
            asm volatile("prefetch.global.L2 [%0];" :: "l"(pa));
            asm volatile("prefetch.global.L2 [%0];" :: "l"(pb));
        }

        const float ys = fmaf((float)(oyb + k), 2.0f / (OH_ - 1), -1.0f);
        const float x  = (fmaf(th1, ys, xc) + 1.0f) * (0.5f * (float)W_);
        const float y  = (fmaf(th4, ys, yc) + 1.0f) * (0.5f * (float)H_);

        const float xf = floorf(x), yf = floorf(y);
        const int ix0 = min(max((int)xf,     0), W_ - 1);
        const int ix1 = min(max((int)xf + 1, 0), W_ - 1);
        const int iy0 = min(max((int)yf,     0), H_ - 1);
        const int iy1 = min(max((int)yf + 1, 0), H_ - 1);

        // ---- unconditional bottom-row loads: branch-free, batchable ----
        const int x0o = ix0 << 4;
        const int x1o = ix1 << 4;
        const int r1o = iy1 << 12;
        const float4 Nb = __ldg(imgb + r1o + x0o);
        const float4 Nd = __ldg(imgb + r1o + x1o);

        // ---- top-row corners: reuse prev bottom pair on exact key match ----
        const int key = ix0 | (ix1 << 8) | (iy0 << 16);
        float4 Na, Nc;
        if (key == pkey) {
            Na = Pb;
            Nc = Pd;
        } else {
            const int r0o = iy0 << 12;
            Na = __ldg(imgb + r0o + x0o);
            Nc = __ldg(imgb + r0o + x1o);
        }
        pkey = ix0 | (ix1 << 8) | (iy1 << 16);

        // weights from CLIPPED corners cast back to float (matches reference)
        const float x0f = (float)ix0, x1f = (float)ix1;
        const float y0f = (float)iy0, y1f = (float)iy1;
        const float wa = (x1f - x) * (y1f - y);
        const float wb = (x1f - x) * (y - y0f);
        const float wc = (x - x0f) * (y1f - y);
        const float wd = (x - x0f) * (y - y0f);

        float4 o;
        o.x = fmaf(wa, Na.x, fmaf(wb, Nb.x, fmaf(wc, Nc.x, wd * Nd.x)));
        o.y = fmaf(wa, Na.y, fmaf(wb, Nb.y, fmaf(wc, Nc.y, wd * Nd.y)));
        o.z = fmaf(wa, Na.z, fmaf(wb, Nb.z, fmaf(wc, Nc.z, wd * Nd.z)));
        o.w = fmaf(wa, Na.w, fmaf(wb, Nb.w, fmaf(wc, Nc.w, wd * Nd.w)));

        *out4 = o;
        out4 += OW_ * (C_ / 4);

        Pb = Nb; Pd = Nd;
    }
}

extern "C" void kernel_launch(void* const* d_in, const int* in_sizes, int n_in,
                              void* d_out, int out_size)
{
    const float* img   = (const float*)d_in[0];
    const float* theta = (const float*)d_in[1];
    float* out = (float*)d_out;

    // threads = B*OW*(OH/K)*16 = 16*256*32*16 = 2,097,152 -> 8192 blocks
    const int threads = 256;
    const int blocks  = (B_ * OW_ * (OH_ / K_) * 16) / threads;

    stn_kernel<<<blocks, threads>>>(img, theta, out);
}

// round 17
// speedup vs baseline: 1.1530x; 1.0155x over previous
#include <cuda_runtime.h>
#include <cstdint>

// SpatialTransformer: affine grid + bilinear sampling.
// cp.async pipelined gather: corner texels are staged gmem->smem with
// cp.async.cg (no dest registers, no scoreboard pressure), S=3 stages deep,
// one commit group per row. Each thread touches only its own smem slots, so
// no block barriers are needed. Within-thread corner reuse is decided at
// ISSUE time (integer key): on reuse the top-corner copies are skipped and
// the previous row's bottom values are STS-forwarded at consume time.
// image: [B=16, H=256, W=256, C=64] fp32, theta: [B=16, 6], out same shape.

constexpr int B_  = 16;
constexpr int H_  = 256;
constexpr int W_  = 256;
constexpr int C_  = 64;
constexpr int OH_ = 256;
constexpr int OW_ = 256;
constexpr int K_  = 8;   // oy pixels per thread (OH_/K_ = 32 strips)
constexpr int S_  = 3;   // pipeline stages

__device__ __forceinline__ void cpasync16(uint32_t smem_addr, const float4* g)
{
    asm volatile("cp.async.cg.shared.global [%0], [%1], 16;"
                 :: "r"(smem_addr), "l"(g) : "memory");
}

__global__ __launch_bounds__(256) void stn_kernel(
    const float* __restrict__ img,
    const float* __restrict__ theta,
    float* __restrict__ out)
{
    __shared__ float4 sNa[S_ * 256];
    __shared__ float4 sNb[S_ * 256];
    __shared__ float4 sNc[S_ * 256];
    __shared__ float4 sNd[S_ * 256];

    const int tid = threadIdx.x;
    const int gid = blockIdx.x * blockDim.x + tid;
    const int c4  = gid & 15;          // float4 chunk (4 channels)
    const int t   = gid >> 4;          // pixel-column index
    const int ox  = t & (OW_ - 1);
    const int t2  = t >> 8;
    const int oyb = (t2 & (OH_ / K_ - 1)) * K_;
    const int b   = t2 >> 5;           // OH_/K_ = 32 -> shift 5

    const float th1 = __ldg(theta + b * 6 + 1);
    const float th4 = __ldg(theta + b * 6 + 4);
    // fold: xt = th1*ys + (th0*xs + th2), yt = th4*ys + (th3*xs + th5)
    const float xs = fmaf((float)ox, 2.0f / (OW_ - 1), -1.0f);
    const float xc = fmaf(__ldg(theta + b * 6 + 0), xs, __ldg(theta + b * 6 + 2));
    const float yc = fmaf(__ldg(theta + b * 6 + 3), xs, __ldg(theta + b * 6 + 5));

    // batch-folded base; per-texel float4 offset = (iy<<12) | (ix<<4)
    const float4* __restrict__ imgb =
        (const float4*)img + c4 + b * (H_ * W_ * (C_ / 4));
    float4* __restrict__ out4 =
        (float4*)out + (((b * OH_ + oyb) * OW_ + ox) * (C_ / 4) + c4);

    const uint32_t aNa = (uint32_t)__cvta_generic_to_shared(sNa + tid);
    const uint32_t aNb = (uint32_t)__cvta_generic_to_shared(sNb + tid);
    const uint32_t aNc = (uint32_t)__cvta_generic_to_shared(sNc + tid);
    const uint32_t aNd = (uint32_t)__cvta_generic_to_shared(sNd + tid);

    int pkeyI = -1;          // issue-side: previous row's bottom key
    unsigned rmask = 0;      // bit j = row j reuses prev bottom pair

    // ---- issue one row's corner copies (2 or 4 x 16B) + commit ----
    auto issue = [&](int j) {
        const float ys = fmaf((float)(oyb + j), 2.0f / (OH_ - 1), -1.0f);
        const float x  = (fmaf(th1, ys, xc) + 1.0f) * (0.5f * (float)W_);
        const float y  = (fmaf(th4, ys, yc) + 1.0f) * (0.5f * (float)H_);
        const float xf = floorf(x), yf = floorf(y);
        const int ix0 = min(max((int)xf,     0), W_ - 1);
        const int ix1 = min(max((int)xf + 1, 0), W_ - 1);
        const int iy0 = min(max((int)yf,     0), H_ - 1);
        const int iy1 = min(max((int)yf + 1, 0), H_ - 1);

        const int keyT = ix0 | (ix1 << 8) | (iy0 << 16);
        const bool ru  = (keyT == pkeyI);
        pkeyI = ix0 | (ix1 << 8) | (iy1 << 16);
        if (ru) rmask |= 1u << j;

        const uint32_t so = (uint32_t)((j % S_) * 256) * 16u;  // slot byte offset
        const int x0o = ix0 << 4, x1o = ix1 << 4;
        const int r1o = iy1 << 12;
        cpasync16(aNb + so, imgb + r1o + x0o);
        cpasync16(aNd + so, imgb + r1o + x1o);
        if (!ru) {
            const int r0o = iy0 << 12;
            cpasync16(aNa + so, imgb + r0o + x0o);
            cpasync16(aNc + so, imgb + r0o + x1o);
        }
        asm volatile("cp.async.commit_group;" ::: "memory");
    };

    // prologue: rows 0..S_-2
#pragma unroll
    for (int j = 0; j < S_ - 1; j++) issue(j);

#pragma unroll
    for (int j = 0; j < K_; j++) {
        if (j + S_ - 1 < K_) issue(j + S_ - 1);
        else asm volatile("cp.async.commit_group;" ::: "memory");  // keep group count uniform
        asm volatile("cp.async.wait_group %0;" :: "n"(S_ - 1) : "memory");

        const int si = (j % S_) * 256 + tid;
        const float4 Na = sNa[si];
        const float4 Nb = sNb[si];
        const float4 Nc = sNc[si];
        const float4 Nd = sNd[si];

        // recompute coords for weights (cheap fp; matches reference exactly)
        const float ys = fmaf((float)(oyb + j), 2.0f / (OH_ - 1), -1.0f);
        const float x  = (fmaf(th1, ys, xc) + 1.0f) * (0.5f * (float)W_);
        const float y  = (fmaf(th4, ys, yc) + 1.0f) * (0.5f * (float)H_);
        const float xf = floorf(x), yf = floorf(y);
        const int ix0 = min(max((int)xf,     0), W_ - 1);
        const int ix1 = min(max((int)xf + 1, 0), W_ - 1);
        const int iy0 = min(max((int)yf,     0), H_ - 1);
        const int iy1 = min(max((int)yf + 1, 0), H_ - 1);
        const float x0f = (float)ix0, x1f = (float)ix1;
        const float y0f = (float)iy0, y1f = (float)iy1;
        const float wa = (x1f - x) * (y1f - y);
        const float wb = (x1f - x) * (y - y0f);
        const float wc = (x - x0f) * (y1f - y);
        const float wd = (x - x0f) * (y - y0f);

        float4 o;
        o.x = fmaf(wa, Na.x, fmaf(wb, Nb.x, fmaf(wc, Nc.x, wd * Nd.x)));
        o.y = fmaf(wa, Na.y, fmaf(wb, Nb.y, fmaf(wc, Nc.y, wd * Nd.y)));
        o.z = fmaf(wa, Na.z, fmaf(wb, Nb.z, fmaf(wc, Nc.z, wd * Nd.z)));
        o.w = fmaf(wa, Na.w, fmaf(wb, Nb.w, fmaf(wc, Nc.w, wd * Nd.w)));

        *out4 = o;
        out4 += OW_ * (C_ / 4);

        // forward bottom pair into row j+1's top slots when it reuses them
        // (safe: reuse rows have no cp.async in flight on Na/Nc addresses)
        if (j + 1 < K_ && ((rmask >> (j + 1)) & 1u)) {
            const int sn = ((j + 1) % S_) * 256 + tid;
            sNa[sn] = Nb;
            sNc[sn] = Nd;
        }
    }
}

extern "C" void kernel_launch(void* const* d_in, const int* in_sizes, int n_in,
                              void* d_out, int out_size)
{
    const float* img   = (const float*)d_in[0];
    const float* theta = (const float*)d_in[1];
    float* out = (float*)d_out;

    // threads = B*OW*(OH/K)*16 = 16*256*32*16 = 2,097,152 -> 8192 blocks
    const int threads = 256;
    const int blocks  = (B_ * OW_ * (OH_ / K_) * 16) / threads;

    stn_kernel<<<blocks, threads>>>(img, theta, out);
}